// round 4
// baseline (speedup 1.0000x reference)
#include <cuda_runtime.h>
#include <math.h>
#include <stdint.h>

// ---------------- problem constants ----------------
#define NB   3
#define Bc   4
#define Tt   512
#define Nf   256
#define Dd   1024
#define DXFc 512
#define Ee   1024
#define Hh   16
#define HDc  64
#define SQ   (NB*Tt)   // 1536
#define SKk  (NB*Nf)   // 768
#define BHc  (Bc*Hh)   // 64
#define EPSV 1e-6f

#define KMAP(k) (((k) & ~7) | (((k) & 3) << 1) | (((k) >> 2) & 1))

// ---------------- scratch ----------------
__device__ float g_mod_x [NB*Bc*2*Dd];
__device__ float g_mod_xf[NB*Bc*2*DXFc];
__device__ float g_xn [NB*Bc*Tt*Dd];
__device__ float g_xfn[NB*Bc*Nf*DXFc];
__device__ float g_Qh[(size_t)BHc*SQ*HDc];
__device__ float g_Kh[(size_t)BHc*SKk*HDc];
__device__ float g_Vh[(size_t)BHc*SKk*HDc];
__device__ float g_att[(size_t)Bc*SQ*Dd];

// ---------------- helpers ----------------
__device__ __forceinline__ uint32_t f2tf32(float f) {
    uint32_t u; asm("cvt.rna.tf32.f32 %0, %1;" : "=r"(u) : "f"(f)); return u;
}
__device__ __forceinline__ void mma_tf32(
    float& d0, float& d1, float& d2, float& d3,
    uint32_t a0, uint32_t a1, uint32_t a2, uint32_t a3,
    uint32_t b0, uint32_t b1)
{
    asm volatile(
        "mma.sync.aligned.m16n8k8.row.col.f32.tf32.tf32.f32 "
        "{%0,%1,%2,%3}, {%4,%5,%6,%7}, {%8,%9}, {%0,%1,%2,%3};"
        : "+f"(d0), "+f"(d1), "+f"(d2), "+f"(d3)
        : "r"(a0), "r"(a1), "r"(a2), "r"(a3), "r"(b0), "r"(b1));
}
__device__ __forceinline__ void cp_async16(void* dst, const void* src) {
    uint32_t s = (uint32_t)__cvta_generic_to_shared(dst);
    asm volatile("cp.async.cg.shared.global [%0], [%1], 16;" :: "r"(s), "l"(src));
}
#define CP_COMMIT() asm volatile("cp.async.commit_group;")
#define CP_WAIT0()  asm volatile("cp.async.wait_group 0;" ::: "memory")

// ---------------- kernel 1: adaLN modulation ----------------
__global__ __launch_bounds__(256) void adaln_mod_kernel(
    const float* __restrict__ emb, const float* __restrict__ w,
    const float* __restrict__ bvec, float* __restrict__ out, int twoD)
{
    __shared__ float se[Ee];
    int b = blockIdx.y, n = blockIdx.z;
    int tid = threadIdx.x;
    for (int i = tid*4; i < Ee; i += 256*4) {
        float4 v = *(const float4*)(emb + (size_t)b*Ee + i);
        se[i+0] = v.x / (1.f + __expf(-v.x));
        se[i+1] = v.y / (1.f + __expf(-v.y));
        se[i+2] = v.z / (1.f + __expf(-v.z));
        se[i+3] = v.w / (1.f + __expf(-v.w));
    }
    __syncthreads();
    int j = blockIdx.x*256 + tid;
    const float* wr = w + ((size_t)n*twoD + j)*Ee;
    float acc = 0.f;
    #pragma unroll 8
    for (int e = 0; e < Ee; e += 4) {
        float4 wv = *(const float4*)(wr + e);
        acc += se[e]*wv.x + se[e+1]*wv.y + se[e+2]*wv.z + se[e+3]*wv.w;
    }
    out[((size_t)n*Bc + b)*twoD + j] = acc + bvec[(size_t)n*twoD + j];
}

// ---------------- kernel 2: LayerNorm + modulate ----------------
__global__ __launch_bounds__(256) void ln_mod_kernel(
    const float* __restrict__ xa, const float* __restrict__ xb,
    const float* __restrict__ xc, const float* __restrict__ mod,
    float* __restrict__ xn, int dim, int rows_per_n, int rows_per_b)
{
    int r  = blockIdx.x;
    int n  = r / rows_per_n;
    int rr = r - n*rows_per_n;
    int b  = rr / rows_per_b;
    const float* xp = (n == 0 ? xa : (n == 1 ? xb : xc)) + (size_t)rr*dim;
    int tid = threadIdx.x;

    float s1 = 0.f, s2 = 0.f;
    for (int d = tid*4; d < dim; d += 1024) {
        float4 v = *(const float4*)(xp + d);
        s1 += v.x + v.y + v.z + v.w;
        s2 += v.x*v.x + v.y*v.y + v.z*v.z + v.w*v.w;
    }
    #pragma unroll
    for (int off = 16; off; off >>= 1) {
        s1 += __shfl_xor_sync(0xffffffffu, s1, off);
        s2 += __shfl_xor_sync(0xffffffffu, s2, off);
    }
    __shared__ float rs1[8], rs2[8];
    int wid = tid >> 5, lane = tid & 31;
    if (!lane) { rs1[wid] = s1; rs2[wid] = s2; }
    __syncthreads();
    s1 = rs1[0]+rs1[1]+rs1[2]+rs1[3]+rs1[4]+rs1[5]+rs1[6]+rs1[7];
    s2 = rs2[0]+rs2[1]+rs2[2]+rs2[3]+rs2[4]+rs2[5]+rs2[6]+rs2[7];

    float inv = 1.f / (float)dim;
    float mu  = s1 * inv;
    float var = s2 * inv - mu*mu;
    float rstd = rsqrtf(var + EPSV);

    const float* sc = mod + ((size_t)n*Bc + b)*2*dim;
    const float* sh = sc + dim;
    float* op = xn + (size_t)r*dim;
    for (int d = tid*4; d < dim; d += 1024) {
        float4 v = *(const float4*)(xp + d);
        float4 s = *(const float4*)(sc + d);
        float4 h = *(const float4*)(sh + d);
        float4 o;
        o.x = (v.x - mu)*rstd*(1.f + s.x) + h.x;
        o.y = (v.y - mu)*rstd*(1.f + s.y) + h.y;
        o.z = (v.z - mu)*rstd*(1.f + s.z) + h.z;
        o.w = (v.w - mu)*rstd*(1.f + s.w) + h.w;
        *(float4*)(op + d) = o;
    }
}

// ---------------- kernel 3: cp.async double-buffered tf32 GEMM ----------------
// Block 128x128, k-slab 32, 8 warps (2x4) each 64x32.
// MODE 0: A per-n contiguous [n][M][K]; C scattered to head layout. Supports a
//         second weight/bias/output set (blockIdx.z in [NB,2NB) -> W1/b1/C1).
// MODE 1: A = g_att rows (b*NB+n)*L + t ; C = [n][M][Nout].
#define GEMM_SMEM (4*128*36*4)   // 2 stages x (A+B) x 128x36 floats
template<int MODE>
__global__ __launch_bounds__(256, 2) void gemm_tc_kernel(
    const float* __restrict__ A,
    const float* __restrict__ W0, const float* __restrict__ b0, float* __restrict__ C0,
    const float* __restrict__ W1, const float* __restrict__ b1, float* __restrict__ C1,
    int M, int Nout, int K, int L)
{
    extern __shared__ float gsh[];
    float* Asm = gsh;               // [2][128][36]
    float* Bsm = gsh + 2*128*36;    // [2][128][36]

    int zz = blockIdx.z;
    int second = (zz >= NB);
    int n = second ? zz - NB : zz;
    const float* W    = second ? W1 : W0;
    const float* bias = second ? b1 : b0;
    float*       C    = second ? C1 : C0;

    int mt = blockIdx.x, nt = blockIdx.y;
    int tid = threadIdx.x;
    int lrow = tid >> 1;
    int lkb  = (tid & 1) * 16;
    int m0 = mt * 128;

    int mrow = m0 + lrow;
    const float* aptr;
    if (MODE == 0) {
        aptr = A + ((size_t)n*M + mrow)*K + lkb;
    } else {
        int bq = mrow / L;
        int tq = mrow - bq*L;
        aptr = A + ((size_t)(bq*NB + n)*L + tq)*K + lkb;
    }
    const float* wptr = W + ((size_t)n*Nout + nt*128 + lrow)*K + lkb;
    float* Ad = Asm + lrow*36 + lkb;
    float* Bd = Bsm + lrow*36 + lkb;

    int wid = tid >> 5, lane = tid & 31;
    int g = lane >> 2, t = lane & 3;
    int wm = wid >> 2, wn = wid & 3;
    int warp_m = wm*64, warp_n = wn*32;

    float acc[4][4][4];
    #pragma unroll
    for (int mi = 0; mi < 4; mi++)
        #pragma unroll
        for (int ni = 0; ni < 4; ni++)
            #pragma unroll
            for (int r = 0; r < 4; r++) acc[mi][ni][r] = 0.f;

    int ntiles = K >> 5;

    // prologue: stage 0
    #pragma unroll
    for (int j = 0; j < 4; j++) {
        cp_async16(Ad + j*4, aptr + j*4);
        cp_async16(Bd + j*4, wptr + j*4);
    }
    CP_COMMIT();

    for (int kt = 0; kt < ntiles; kt++) {
        CP_WAIT0();
        __syncthreads();

        if (kt + 1 < ntiles) {
            int nb = (kt+1) & 1;
            int ko = (kt+1) * 32;
            #pragma unroll
            for (int j = 0; j < 4; j++) {
                cp_async16(Ad + nb*4608 + j*4, aptr + ko + j*4);
                cp_async16(Bd + nb*4608 + j*4, wptr + ko + j*4);
            }
            CP_COMMIT();
        }

        const float* Ab = Asm + (kt & 1)*4608;
        const float* Bb = Bsm + (kt & 1)*4608;
        #pragma unroll
        for (int k0 = 0; k0 < 32; k0 += 8) {
            uint32_t af[4][4], bf[4][2];
            #pragma unroll
            for (int mi = 0; mi < 4; mi++) {
                int r0 = warp_m + mi*16 + g;
                af[mi][0] = f2tf32(Ab[r0*36     + k0 + t]);
                af[mi][1] = f2tf32(Ab[(r0+8)*36 + k0 + t]);
                af[mi][2] = f2tf32(Ab[r0*36     + k0 + t + 4]);
                af[mi][3] = f2tf32(Ab[(r0+8)*36 + k0 + t + 4]);
            }
            #pragma unroll
            for (int ni = 0; ni < 4; ni++) {
                int c = warp_n + ni*8 + g;
                bf[ni][0] = f2tf32(Bb[c*36 + k0 + t]);
                bf[ni][1] = f2tf32(Bb[c*36 + k0 + t + 4]);
            }
            #pragma unroll
            for (int mi = 0; mi < 4; mi++)
                #pragma unroll
                for (int ni = 0; ni < 4; ni++)
                    mma_tf32(acc[mi][ni][0], acc[mi][ni][1],
                             acc[mi][ni][2], acc[mi][ni][3],
                             af[mi][0], af[mi][1], af[mi][2], af[mi][3],
                             bf[ni][0], bf[ni][1]);
        }
    }

    #pragma unroll
    for (int mi = 0; mi < 4; mi++) {
        int rbase = m0 + warp_m + mi*16 + g;
        #pragma unroll
        for (int ni = 0; ni < 4; ni++) {
            int col = nt*128 + warp_n + ni*8 + t*2;
            float2 bv = *(const float2*)(bias + (size_t)n*Nout + col);
            #pragma unroll
            for (int h2 = 0; h2 < 2; h2++) {
                int row = rbase + h2*8;
                float2 o;
                o.x = acc[mi][ni][h2*2+0] + bv.x;
                o.y = acc[mi][ni][h2*2+1] + bv.y;
                if (MODE == 0) {
                    int bq = row / L; int l = row - bq*L;
                    int hh = col >> 6; int hd = col & 63;
                    size_t idx = (((size_t)(bq*Hh + hh))*((size_t)NB*L)
                                  + (size_t)n*L + l)*HDc + hd;
                    *(float2*)(C + idx) = o;
                } else {
                    *(float2*)(C + ((size_t)n*M + row)*Nout + col) = o;
                }
            }
        }
    }
}

// ---------------- kernel 4: tf32 tensor-core flash attention ----------------
#define ATTN_SMEM_BYTES (27648*4)
__global__ __launch_bounds__(256, 2) void attn_tc_kernel(
    const float* __restrict__ Q, const float* __restrict__ K,
    const float* __restrict__ V, float* __restrict__ O)
{
    extern __shared__ uint32_t sh[];
    uint32_t* Qs = sh;            // [128][72]
    uint32_t* Ks = sh + 9216;     // [64][72]
    uint32_t* Vs = sh + 13824;    // [64][72]
    uint32_t* Ps = sh + 18432;    // [128][72]

    int qt = blockIdx.x, bh = blockIdx.y;
    int tid = threadIdx.x;
    int wid = tid >> 5, lane = tid & 31;
    int g = lane >> 2, t = lane & 3;
    int r0 = wid*16 + g, r1 = r0 + 8;

    {
        int lrow = tid >> 1, lk = (tid & 1) * 32;
        const float* src = Q + ((size_t)bh*SQ + qt*128 + lrow)*HDc + lk;
        uint32_t* dst = Qs + lrow*72;
        #pragma unroll
        for (int j = 0; j < 8; j++) {
            float4 v = *(const float4*)(src + j*4);
            int d0 = lk + j*4;
            dst[KMAP(d0+0)] = f2tf32(v.x*0.125f);
            dst[KMAP(d0+1)] = f2tf32(v.y*0.125f);
            dst[KMAP(d0+2)] = f2tf32(v.z*0.125f);
            dst[KMAP(d0+3)] = f2tf32(v.w*0.125f);
        }
    }

    float m0 = -3.0e38f, m1 = -3.0e38f, l0 = 0.f, l1 = 0.f;
    float acc[8][4];
    #pragma unroll
    for (int ni = 0; ni < 8; ni++)
        #pragma unroll
        for (int r = 0; r < 4; r++) acc[ni][r] = 0.f;

    for (int kt = 0; kt < SKk/64; kt++) {
        {
            int lrow = tid >> 2, lk = (tid & 3) * 16;
            const float* kp = K + ((size_t)bh*SKk + kt*64 + lrow)*HDc + lk;
            const float* vp = V + ((size_t)bh*SKk + kt*64 + lrow)*HDc + lk;
            uint32_t* kd = Ks + lrow*72;
            uint32_t* vd = Vs + lrow*72 + lk;
            #pragma unroll
            for (int j = 0; j < 4; j++) {
                float4 kv = *(const float4*)(kp + j*4);
                int d0 = lk + j*4;
                kd[KMAP(d0+0)] = f2tf32(kv.x);
                kd[KMAP(d0+1)] = f2tf32(kv.y);
                kd[KMAP(d0+2)] = f2tf32(kv.z);
                kd[KMAP(d0+3)] = f2tf32(kv.w);
                float4 vv = *(const float4*)(vp + j*4);
                uint4 pk;
                pk.x = f2tf32(vv.x); pk.y = f2tf32(vv.y);
                pk.z = f2tf32(vv.z); pk.w = f2tf32(vv.w);
                *(uint4*)(vd + j*4) = pk;
            }
        }
        __syncthreads();

        float sf[8][4];
        #pragma unroll
        for (int ni = 0; ni < 8; ni++)
            #pragma unroll
            for (int r = 0; r < 4; r++) sf[ni][r] = 0.f;

        #pragma unroll
        for (int k0 = 0; k0 < 8; k0++) {
            uint2 aA = *(const uint2*)&Qs[r0*72 + k0*8 + 2*t];
            uint2 aB = *(const uint2*)&Qs[r1*72 + k0*8 + 2*t];
            #pragma unroll
            for (int ni = 0; ni < 8; ni++) {
                uint2 b = *(const uint2*)&Ks[(ni*8+g)*72 + k0*8 + 2*t];
                mma_tf32(sf[ni][0], sf[ni][1], sf[ni][2], sf[ni][3],
                         aA.x, aB.x, aA.y, aB.y, b.x, b.y);
            }
        }

        float mx0 = -3.0e38f, mx1 = -3.0e38f;
        #pragma unroll
        for (int ni = 0; ni < 8; ni++) {
            mx0 = fmaxf(mx0, fmaxf(sf[ni][0], sf[ni][1]));
            mx1 = fmaxf(mx1, fmaxf(sf[ni][2], sf[ni][3]));
        }
        mx0 = fmaxf(mx0, __shfl_xor_sync(0xffffffffu, mx0, 1));
        mx0 = fmaxf(mx0, __shfl_xor_sync(0xffffffffu, mx0, 2));
        mx1 = fmaxf(mx1, __shfl_xor_sync(0xffffffffu, mx1, 1));
        mx1 = fmaxf(mx1, __shfl_xor_sync(0xffffffffu, mx1, 2));
        float mn0 = fmaxf(m0, mx0), mn1 = fmaxf(m1, mx1);
        float rs0 = __expf(m0 - mn0), rs1 = __expf(m1 - mn1);
        float ls0 = 0.f, ls1 = 0.f;
        #pragma unroll
        for (int ni = 0; ni < 8; ni++) {
            sf[ni][0] = __expf(sf[ni][0] - mn0);
            sf[ni][1] = __expf(sf[ni][1] - mn0);
            sf[ni][2] = __expf(sf[ni][2] - mn1);
            sf[ni][3] = __expf(sf[ni][3] - mn1);
            ls0 += sf[ni][0] + sf[ni][1];
            ls1 += sf[ni][2] + sf[ni][3];
        }
        ls0 += __shfl_xor_sync(0xffffffffu, ls0, 1);
        ls0 += __shfl_xor_sync(0xffffffffu, ls0, 2);
        ls1 += __shfl_xor_sync(0xffffffffu, ls1, 1);
        ls1 += __shfl_xor_sync(0xffffffffu, ls1, 2);
        l0 = l0*rs0 + ls0;  m0 = mn0;
        l1 = l1*rs1 + ls1;  m1 = mn1;
        #pragma unroll
        for (int ni = 0; ni < 8; ni++) {
            acc[ni][0] *= rs0; acc[ni][1] *= rs0;
            acc[ni][2] *= rs1; acc[ni][3] *= rs1;
        }

        #pragma unroll
        for (int ni = 0; ni < 8; ni++) {
            Ps[r0*72 + ni*8 + KMAP(2*t)  ] = f2tf32(sf[ni][0]);
            Ps[r0*72 + ni*8 + KMAP(2*t+1)] = f2tf32(sf[ni][1]);
            Ps[r1*72 + ni*8 + KMAP(2*t)  ] = f2tf32(sf[ni][2]);
            Ps[r1*72 + ni*8 + KMAP(2*t+1)] = f2tf32(sf[ni][3]);
        }
        __syncwarp();

        #pragma unroll
        for (int k0 = 0; k0 < 8; k0++) {
            uint2 aA = *(const uint2*)&Ps[r0*72 + k0*8 + 2*t];
            uint2 aB = *(const uint2*)&Ps[r1*72 + k0*8 + 2*t];
            #pragma unroll
            for (int ni = 0; ni < 8; ni++) {
                uint32_t b0 = Vs[(k0*8 + t    )*72 + ni*8 + g];
                uint32_t b1 = Vs[(k0*8 + t + 4)*72 + ni*8 + g];
                mma_tf32(acc[ni][0], acc[ni][1], acc[ni][2], acc[ni][3],
                         aA.x, aB.x, aA.y, aB.y, b0, b1);
            }
        }
        __syncthreads();
    }

    float inv0 = 1.f / l0, inv1 = 1.f / l1;
    int b = bh >> 4, h = bh & 15;
    int q0 = qt*128 + r0, q1 = q0 + 8;
    float* O0 = O + ((size_t)b*SQ + q0)*Dd + h*64;
    float* O1 = O + ((size_t)b*SQ + q1)*Dd + h*64;
    #pragma unroll
    for (int ni = 0; ni < 8; ni++) {
        int col = ni*8 + 2*t;
        float2 o0, o1;
        o0.x = acc[ni][0]*inv0; o0.y = acc[ni][1]*inv0;
        o1.x = acc[ni][2]*inv1; o1.y = acc[ni][3]*inv1;
        *(float2*)(O0 + col) = o0;
        *(float2*)(O1 + col) = o1;
    }
}

// ---------------- launch ----------------
extern "C" void kernel_launch(void* const* d_in, const int* in_sizes, int n_in,
                              void* d_out, int out_size)
{
    const float* x1   = (const float*)d_in[0];
    const float* x2   = (const float*)d_in[1];
    const float* x3   = (const float*)d_in[2];
    const float* xf1  = (const float*)d_in[3];
    const float* xf2  = (const float*)d_in[4];
    const float* xf3  = (const float*)d_in[5];
    const float* emb  = (const float*)d_in[6];
    const float* axw  = (const float*)d_in[7];
    const float* axb  = (const float*)d_in[8];
    const float* afw  = (const float*)d_in[9];
    const float* afb  = (const float*)d_in[10];
    const float* q_w  = (const float*)d_in[11];
    const float* q_b  = (const float*)d_in[12];
    const float* k_w  = (const float*)d_in[13];
    const float* k_b  = (const float*)d_in[14];
    const float* v_w  = (const float*)d_in[15];
    const float* v_b  = (const float*)d_in[16];
    const float* o_w  = (const float*)d_in[17];
    const float* o_b  = (const float*)d_in[18];
    float* out = (float*)d_out;

    float *mx, *mxf, *xn, *xfn, *Qp, *Kp, *Vp, *att;
    cudaGetSymbolAddress((void**)&mx,  g_mod_x);
    cudaGetSymbolAddress((void**)&mxf, g_mod_xf);
    cudaGetSymbolAddress((void**)&xn,  g_xn);
    cudaGetSymbolAddress((void**)&xfn, g_xfn);
    cudaGetSymbolAddress((void**)&Qp,  g_Qh);
    cudaGetSymbolAddress((void**)&Kp,  g_Kh);
    cudaGetSymbolAddress((void**)&Vp,  g_Vh);
    cudaGetSymbolAddress((void**)&att, g_att);

    cudaFuncSetAttribute(attn_tc_kernel,
        cudaFuncAttributeMaxDynamicSharedMemorySize, ATTN_SMEM_BYTES);
    cudaFuncSetAttribute(gemm_tc_kernel<0>,
        cudaFuncAttributeMaxDynamicSharedMemorySize, GEMM_SMEM);
    cudaFuncSetAttribute(gemm_tc_kernel<1>,
        cudaFuncAttributeMaxDynamicSharedMemorySize, GEMM_SMEM);

    adaln_mod_kernel<<<dim3(2*Dd/256,   Bc, NB), 256>>>(emb, axw, axb, mx,  2*Dd);
    adaln_mod_kernel<<<dim3(2*DXFc/256, Bc, NB), 256>>>(emb, afw, afb, mxf, 2*DXFc);

    ln_mod_kernel<<<NB*Bc*Tt, 256>>>(x1, x2, x3, mx,  xn,  Dd,   Bc*Tt, Tt);
    ln_mod_kernel<<<NB*Bc*Nf, 256>>>(xf1, xf2, xf3, mxf, xfn, DXFc, Bc*Nf, Nf);

    // Q projection
    gemm_tc_kernel<0><<<dim3(Bc*Tt/128, Dd/128, NB), 256, GEMM_SMEM>>>(
        xn, q_w, q_b, Qp, q_w, q_b, Qp, Bc*Tt, Dd, Dd, Tt);
    // K + V projections fused in one launch (z in [0,NB) -> K set, [NB,2NB) -> V set)
    gemm_tc_kernel<0><<<dim3(Bc*Nf/128, Dd/128, 2*NB), 256, GEMM_SMEM>>>(
        xfn, k_w, k_b, Kp, v_w, v_b, Vp, Bc*Nf, Dd, DXFc, Nf);

    attn_tc_kernel<<<dim3(SQ/128, BHc), 256, ATTN_SMEM_BYTES>>>(Qp, Kp, Vp, att);

    gemm_tc_kernel<1><<<dim3(Bc*Tt/128, Dd/128, NB), 256, GEMM_SMEM>>>(
        att, o_w, o_b, out, o_w, o_b, out, Bc*Tt, Dd, Dd, Tt);
}

// round 5
// speedup vs baseline: 1.0174x; 1.0174x over previous
#include <cuda_runtime.h>
#include <math.h>
#include <stdint.h>

// ---------------- problem constants ----------------
#define NB   3
#define Bc   4
#define Tt   512
#define Nf   256
#define Dd   1024
#define DXFc 512
#define Ee   1024
#define Hh   16
#define HDc  64
#define SQ   (NB*Tt)   // 1536
#define SKk  (NB*Nf)   // 768
#define BHc  (Bc*Hh)   // 64
#define EPSV 1e-6f

#define KMAP(k) (((k) & ~7) | (((k) & 3) << 1) | (((k) >> 2) & 1))

// ---------------- scratch ----------------
__device__ float g_mod_x [NB*Bc*2*Dd];
__device__ float g_mod_xf[NB*Bc*2*DXFc];
__device__ float g_xn [NB*Bc*Tt*Dd];
__device__ float g_xfn[NB*Bc*Nf*DXFc];
__device__ float g_Qh[(size_t)BHc*SQ*HDc];
__device__ float g_Kh[(size_t)BHc*SKk*HDc];
__device__ float g_Vh[(size_t)BHc*SKk*HDc];
__device__ float g_att[(size_t)Bc*SQ*Dd];
// tf32-pre-rounded weights
__device__ float g_qw[NB*Dd*Dd];
__device__ float g_kw[NB*Dd*DXFc];
__device__ float g_vw[NB*Dd*DXFc];
__device__ float g_ow[NB*Dd*Dd];

// ---------------- helpers ----------------
__device__ __forceinline__ uint32_t f2tf32(float f) {
    uint32_t u; asm("cvt.rna.tf32.f32 %0, %1;" : "=r"(u) : "f"(f)); return u;
}
__device__ __forceinline__ float rnd_tf32(float f) {
    return __uint_as_float(f2tf32(f));
}
__device__ __forceinline__ void mma_tf32(
    float& d0, float& d1, float& d2, float& d3,
    uint32_t a0, uint32_t a1, uint32_t a2, uint32_t a3,
    uint32_t b0, uint32_t b1)
{
    asm volatile(
        "mma.sync.aligned.m16n8k8.row.col.f32.tf32.tf32.f32 "
        "{%0,%1,%2,%3}, {%4,%5,%6,%7}, {%8,%9}, {%0,%1,%2,%3};"
        : "+f"(d0), "+f"(d1), "+f"(d2), "+f"(d3)
        : "r"(a0), "r"(a1), "r"(a2), "r"(a3), "r"(b0), "r"(b1));
}
__device__ __forceinline__ void cp_async16(void* dst, const void* src) {
    uint32_t s = (uint32_t)__cvta_generic_to_shared(dst);
    asm volatile("cp.async.cg.shared.global [%0], [%1], 16;" :: "r"(s), "l"(src));
}
#define CP_COMMIT() asm volatile("cp.async.commit_group;")
#define CP_WAIT0()  asm volatile("cp.async.wait_group 0;" ::: "memory")

// ---------------- kernel 0: round weights to tf32 ----------------
__global__ __launch_bounds__(256) void round_w_kernel(
    const float* __restrict__ src, float* __restrict__ dst, int n4)
{
    int i = blockIdx.x*256 + threadIdx.x;
    if (i < n4) {
        float4 v = ((const float4*)src)[i];
        v.x = rnd_tf32(v.x); v.y = rnd_tf32(v.y);
        v.z = rnd_tf32(v.z); v.w = rnd_tf32(v.w);
        ((float4*)dst)[i] = v;
    }
}

// ---------------- kernel 1: adaLN modulation ----------------
__global__ __launch_bounds__(256) void adaln_mod_kernel(
    const float* __restrict__ emb, const float* __restrict__ w,
    const float* __restrict__ bvec, float* __restrict__ out, int twoD)
{
    __shared__ float se[Ee];
    int b = blockIdx.y, n = blockIdx.z;
    int tid = threadIdx.x;
    for (int i = tid*4; i < Ee; i += 256*4) {
        float4 v = *(const float4*)(emb + (size_t)b*Ee + i);
        se[i+0] = v.x / (1.f + __expf(-v.x));
        se[i+1] = v.y / (1.f + __expf(-v.y));
        se[i+2] = v.z / (1.f + __expf(-v.z));
        se[i+3] = v.w / (1.f + __expf(-v.w));
    }
    __syncthreads();
    int j = blockIdx.x*256 + tid;
    const float* wr = w + ((size_t)n*twoD + j)*Ee;
    float acc = 0.f;
    #pragma unroll 8
    for (int e = 0; e < Ee; e += 4) {
        float4 wv = *(const float4*)(wr + e);
        acc += se[e]*wv.x + se[e+1]*wv.y + se[e+2]*wv.z + se[e+3]*wv.w;
    }
    out[((size_t)n*Bc + b)*twoD + j] = acc + bvec[(size_t)n*twoD + j];
}

// ---------------- kernel 2: LayerNorm + modulate (tf32-rounded output) ----------------
__global__ __launch_bounds__(256) void ln_mod_kernel(
    const float* __restrict__ xa, const float* __restrict__ xb,
    const float* __restrict__ xc, const float* __restrict__ mod,
    float* __restrict__ xn, int dim, int rows_per_n, int rows_per_b)
{
    int r  = blockIdx.x;
    int n  = r / rows_per_n;
    int rr = r - n*rows_per_n;
    int b  = rr / rows_per_b;
    const float* xp = (n == 0 ? xa : (n == 1 ? xb : xc)) + (size_t)rr*dim;
    int tid = threadIdx.x;

    float s1 = 0.f, s2 = 0.f;
    for (int d = tid*4; d < dim; d += 1024) {
        float4 v = *(const float4*)(xp + d);
        s1 += v.x + v.y + v.z + v.w;
        s2 += v.x*v.x + v.y*v.y + v.z*v.z + v.w*v.w;
    }
    #pragma unroll
    for (int off = 16; off; off >>= 1) {
        s1 += __shfl_xor_sync(0xffffffffu, s1, off);
        s2 += __shfl_xor_sync(0xffffffffu, s2, off);
    }
    __shared__ float rs1[8], rs2[8];
    int wid = tid >> 5, lane = tid & 31;
    if (!lane) { rs1[wid] = s1; rs2[wid] = s2; }
    __syncthreads();
    s1 = rs1[0]+rs1[1]+rs1[2]+rs1[3]+rs1[4]+rs1[5]+rs1[6]+rs1[7];
    s2 = rs2[0]+rs2[1]+rs2[2]+rs2[3]+rs2[4]+rs2[5]+rs2[6]+rs2[7];

    float inv = 1.f / (float)dim;
    float mu  = s1 * inv;
    float var = s2 * inv - mu*mu;
    float rstd = rsqrtf(var + EPSV);

    const float* sc = mod + ((size_t)n*Bc + b)*2*dim;
    const float* sh = sc + dim;
    float* op = xn + (size_t)r*dim;
    for (int d = tid*4; d < dim; d += 1024) {
        float4 v = *(const float4*)(xp + d);
        float4 s = *(const float4*)(sc + d);
        float4 h = *(const float4*)(sh + d);
        float4 o;
        o.x = rnd_tf32((v.x - mu)*rstd*(1.f + s.x) + h.x);
        o.y = rnd_tf32((v.y - mu)*rstd*(1.f + s.y) + h.y);
        o.z = rnd_tf32((v.z - mu)*rstd*(1.f + s.z) + h.z);
        o.w = rnd_tf32((v.w - mu)*rstd*(1.f + s.w) + h.w);
        *(float4*)(op + d) = o;
    }
}

// ---------------- kernel 3: cp.async tf32 GEMM, LDS.64 frags, no in-loop cvt ----------------
// Inputs A and W MUST already be tf32-rounded values stored as f32.
#define GS_STRIDE 40
#define GS_STAGE  (128*GS_STRIDE)            // floats per stage per operand
#define GEMM_SMEM (4*GS_STAGE*4)             // 2 stages x (A+B), bytes = 81920
template<int MODE>
__global__ __launch_bounds__(256, 2) void gemm_tc_kernel(
    const float* __restrict__ A,
    const float* __restrict__ W0, const float* __restrict__ b0, float* __restrict__ C0,
    const float* __restrict__ W1, const float* __restrict__ b1, float* __restrict__ C1,
    int M, int Nout, int K, int L)
{
    extern __shared__ float gsh[];
    float* Asm = gsh;                 // [2][128][40]
    float* Bsm = gsh + 2*GS_STAGE;    // [2][128][40]

    int zz = blockIdx.z;
    int second = (zz >= NB);
    int n = second ? zz - NB : zz;
    const float* W    = second ? W1 : W0;
    const float* bias = second ? b1 : b0;
    float*       C    = second ? C1 : C0;

    int mt = blockIdx.x, nt = blockIdx.y;
    int tid = threadIdx.x;
    int lrow = tid >> 1;
    int lkb  = (tid & 1) * 16;
    int m0 = mt * 128;

    int mrow = m0 + lrow;
    const float* aptr;
    if (MODE == 0) {
        aptr = A + ((size_t)n*M + mrow)*K + lkb;
    } else {
        int bq = mrow / L;
        int tq = mrow - bq*L;
        aptr = A + ((size_t)(bq*NB + n)*L + tq)*K + lkb;
    }
    const float* wptr = W + ((size_t)n*Nout + nt*128 + lrow)*K + lkb;
    float* Ad = Asm + lrow*GS_STRIDE + lkb;
    float* Bd = Bsm + lrow*GS_STRIDE + lkb;

    int wid = tid >> 5, lane = tid & 31;
    int g = lane >> 2, t = lane & 3;
    int wm = wid >> 2, wn = wid & 3;
    int warp_m = wm*64, warp_n = wn*32;

    float acc[4][4][4];
    #pragma unroll
    for (int mi = 0; mi < 4; mi++)
        #pragma unroll
        for (int ni = 0; ni < 4; ni++)
            #pragma unroll
            for (int r = 0; r < 4; r++) acc[mi][ni][r] = 0.f;

    int ntiles = K >> 5;

    #pragma unroll
    for (int j = 0; j < 4; j++) {
        cp_async16(Ad + j*4, aptr + j*4);
        cp_async16(Bd + j*4, wptr + j*4);
    }
    CP_COMMIT();

    for (int kt = 0; kt < ntiles; kt++) {
        CP_WAIT0();
        __syncthreads();

        if (kt + 1 < ntiles) {
            int nb = (kt+1) & 1;
            int ko = (kt+1) * 32;
            #pragma unroll
            for (int j = 0; j < 4; j++) {
                cp_async16(Ad + nb*GS_STAGE + j*4, aptr + ko + j*4);
                cp_async16(Bd + nb*GS_STAGE + j*4, wptr + ko + j*4);
            }
            CP_COMMIT();
        }

        const float* Ab = Asm + (kt & 1)*GS_STAGE;
        const float* Bb = Bsm + (kt & 1)*GS_STAGE;
        #pragma unroll
        for (int k0 = 0; k0 < 32; k0 += 8) {
            // k-permutation: physical cols (2t, 2t+1) feed k-slots (t, t+4)
            // for BOTH A and B -> dot product unchanged.
            uint2 afa[4], afb[4], bf[4];
            #pragma unroll
            for (int mi = 0; mi < 4; mi++) {
                int r0 = warp_m + mi*16 + g;
                afa[mi] = *(const uint2*)&Ab[r0*GS_STRIDE     + k0 + 2*t];
                afb[mi] = *(const uint2*)&Ab[(r0+8)*GS_STRIDE + k0 + 2*t];
            }
            #pragma unroll
            for (int ni = 0; ni < 4; ni++) {
                int c = warp_n + ni*8 + g;
                bf[ni] = *(const uint2*)&Bb[c*GS_STRIDE + k0 + 2*t];
            }
            #pragma unroll
            for (int mi = 0; mi < 4; mi++)
                #pragma unroll
                for (int ni = 0; ni < 4; ni++)
                    mma_tf32(acc[mi][ni][0], acc[mi][ni][1],
                             acc[mi][ni][2], acc[mi][ni][3],
                             afa[mi].x, afb[mi].x, afa[mi].y, afb[mi].y,
                             bf[ni].x, bf[ni].y);
        }
    }

    #pragma unroll
    for (int mi = 0; mi < 4; mi++) {
        int rbase = m0 + warp_m + mi*16 + g;
        #pragma unroll
        for (int ni = 0; ni < 4; ni++) {
            int col = nt*128 + warp_n + ni*8 + t*2;
            float2 bv = *(const float2*)(bias + (size_t)n*Nout + col);
            #pragma unroll
            for (int h2 = 0; h2 < 2; h2++) {
                int row = rbase + h2*8;
                float2 o;
                o.x = acc[mi][ni][h2*2+0] + bv.x;
                o.y = acc[mi][ni][h2*2+1] + bv.y;
                if (MODE == 0) {
                    int bq = row / L; int l = row - bq*L;
                    int hh = col >> 6; int hd = col & 63;
                    size_t idx = (((size_t)(bq*Hh + hh))*((size_t)NB*L)
                                  + (size_t)n*L + l)*HDc + hd;
                    *(float2*)(C + idx) = o;
                } else {
                    *(float2*)(C + ((size_t)n*M + row)*Nout + col) = o;
                }
            }
        }
    }
}

// ---------------- kernel 4: tf32 flash attention (tf32-rounded output) ----------------
#define ATTN_SMEM_BYTES (27648*4)
__global__ __launch_bounds__(256, 2) void attn_tc_kernel(
    const float* __restrict__ Q, const float* __restrict__ K,
    const float* __restrict__ V, float* __restrict__ O)
{
    extern __shared__ uint32_t sh[];
    uint32_t* Qs = sh;            // [128][72]
    uint32_t* Ks = sh + 9216;     // [64][72]
    uint32_t* Vs = sh + 13824;    // [64][72]
    uint32_t* Ps = sh + 18432;    // [128][72]

    int qt = blockIdx.x, bh = blockIdx.y;
    int tid = threadIdx.x;
    int wid = tid >> 5, lane = tid & 31;
    int g = lane >> 2, t = lane & 3;
    int r0 = wid*16 + g, r1 = r0 + 8;

    {
        int lrow = tid >> 1, lk = (tid & 1) * 32;
        const float* src = Q + ((size_t)bh*SQ + qt*128 + lrow)*HDc + lk;
        uint32_t* dst = Qs + lrow*72;
        #pragma unroll
        for (int j = 0; j < 8; j++) {
            float4 v = *(const float4*)(src + j*4);
            int d0 = lk + j*4;
            dst[KMAP(d0+0)] = f2tf32(v.x*0.125f);
            dst[KMAP(d0+1)] = f2tf32(v.y*0.125f);
            dst[KMAP(d0+2)] = f2tf32(v.z*0.125f);
            dst[KMAP(d0+3)] = f2tf32(v.w*0.125f);
        }
    }

    float m0 = -3.0e38f, m1 = -3.0e38f, l0 = 0.f, l1 = 0.f;
    float acc[8][4];
    #pragma unroll
    for (int ni = 0; ni < 8; ni++)
        #pragma unroll
        for (int r = 0; r < 4; r++) acc[ni][r] = 0.f;

    for (int kt = 0; kt < SKk/64; kt++) {
        {
            int lrow = tid >> 2, lk = (tid & 3) * 16;
            const float* kp = K + ((size_t)bh*SKk + kt*64 + lrow)*HDc + lk;
            const float* vp = V + ((size_t)bh*SKk + kt*64 + lrow)*HDc + lk;
            uint32_t* kd = Ks + lrow*72;
            uint32_t* vd = Vs + lrow*72 + lk;
            #pragma unroll
            for (int j = 0; j < 4; j++) {
                float4 kv = *(const float4*)(kp + j*4);
                int d0 = lk + j*4;
                kd[KMAP(d0+0)] = f2tf32(kv.x);
                kd[KMAP(d0+1)] = f2tf32(kv.y);
                kd[KMAP(d0+2)] = f2tf32(kv.z);
                kd[KMAP(d0+3)] = f2tf32(kv.w);
                float4 vv = *(const float4*)(vp + j*4);
                uint4 pk;
                pk.x = f2tf32(vv.x); pk.y = f2tf32(vv.y);
                pk.z = f2tf32(vv.z); pk.w = f2tf32(vv.w);
                *(uint4*)(vd + j*4) = pk;
            }
        }
        __syncthreads();

        float sf[8][4];
        #pragma unroll
        for (int ni = 0; ni < 8; ni++)
            #pragma unroll
            for (int r = 0; r < 4; r++) sf[ni][r] = 0.f;

        #pragma unroll
        for (int k0 = 0; k0 < 8; k0++) {
            uint2 aA = *(const uint2*)&Qs[r0*72 + k0*8 + 2*t];
            uint2 aB = *(const uint2*)&Qs[r1*72 + k0*8 + 2*t];
            #pragma unroll
            for (int ni = 0; ni < 8; ni++) {
                uint2 b = *(const uint2*)&Ks[(ni*8+g)*72 + k0*8 + 2*t];
                mma_tf32(sf[ni][0], sf[ni][1], sf[ni][2], sf[ni][3],
                         aA.x, aB.x, aA.y, aB.y, b.x, b.y);
            }
        }

        float mx0 = -3.0e38f, mx1 = -3.0e38f;
        #pragma unroll
        for (int ni = 0; ni < 8; ni++) {
            mx0 = fmaxf(mx0, fmaxf(sf[ni][0], sf[ni][1]));
            mx1 = fmaxf(mx1, fmaxf(sf[ni][2], sf[ni][3]));
        }
        mx0 = fmaxf(mx0, __shfl_xor_sync(0xffffffffu, mx0, 1));
        mx0 = fmaxf(mx0, __shfl_xor_sync(0xffffffffu, mx0, 2));
        mx1 = fmaxf(mx1, __shfl_xor_sync(0xffffffffu, mx1, 1));
        mx1 = fmaxf(mx1, __shfl_xor_sync(0xffffffffu, mx1, 2));
        float mn0 = fmaxf(m0, mx0), mn1 = fmaxf(m1, mx1);
        float rs0 = __expf(m0 - mn0), rs1 = __expf(m1 - mn1);
        float ls0 = 0.f, ls1 = 0.f;
        #pragma unroll
        for (int ni = 0; ni < 8; ni++) {
            sf[ni][0] = __expf(sf[ni][0] - mn0);
            sf[ni][1] = __expf(sf[ni][1] - mn0);
            sf[ni][2] = __expf(sf[ni][2] - mn1);
            sf[ni][3] = __expf(sf[ni][3] - mn1);
            ls0 += sf[ni][0] + sf[ni][1];
            ls1 += sf[ni][2] + sf[ni][3];
        }
        ls0 += __shfl_xor_sync(0xffffffffu, ls0, 1);
        ls0 += __shfl_xor_sync(0xffffffffu, ls0, 2);
        ls1 += __shfl_xor_sync(0xffffffffu, ls1, 1);
        ls1 += __shfl_xor_sync(0xffffffffu, ls1, 2);
        l0 = l0*rs0 + ls0;  m0 = mn0;
        l1 = l1*rs1 + ls1;  m1 = mn1;
        #pragma unroll
        for (int ni = 0; ni < 8; ni++) {
            acc[ni][0] *= rs0; acc[ni][1] *= rs0;
            acc[ni][2] *= rs1; acc[ni][3] *= rs1;
        }

        #pragma unroll
        for (int ni = 0; ni < 8; ni++) {
            Ps[r0*72 + ni*8 + KMAP(2*t)  ] = f2tf32(sf[ni][0]);
            Ps[r0*72 + ni*8 + KMAP(2*t+1)] = f2tf32(sf[ni][1]);
            Ps[r1*72 + ni*8 + KMAP(2*t)  ] = f2tf32(sf[ni][2]);
            Ps[r1*72 + ni*8 + KMAP(2*t+1)] = f2tf32(sf[ni][3]);
        }
        __syncwarp();

        #pragma unroll
        for (int k0 = 0; k0 < 8; k0++) {
            uint2 aA = *(const uint2*)&Ps[r0*72 + k0*8 + 2*t];
            uint2 aB = *(const uint2*)&Ps[r1*72 + k0*8 + 2*t];
            #pragma unroll
            for (int ni = 0; ni < 8; ni++) {
                uint32_t b0 = Vs[(k0*8 + t    )*72 + ni*8 + g];
                uint32_t b1 = Vs[(k0*8 + t + 4)*72 + ni*8 + g];
                mma_tf32(acc[ni][0], acc[ni][1], acc[ni][2], acc[ni][3],
                         aA.x, aB.x, aA.y, aB.y, b0, b1);
            }
        }
        __syncthreads();
    }

    float inv0 = 1.f / l0, inv1 = 1.f / l1;
    int b = bh >> 4, h = bh & 15;
    int q0 = qt*128 + r0, q1 = q0 + 8;
    float* O0 = O + ((size_t)b*SQ + q0)*Dd + h*64;
    float* O1 = O + ((size_t)b*SQ + q1)*Dd + h*64;
    #pragma unroll
    for (int ni = 0; ni < 8; ni++) {
        int col = ni*8 + 2*t;
        float2 o0, o1;
        o0.x = rnd_tf32(acc[ni][0]*inv0); o0.y = rnd_tf32(acc[ni][1]*inv0);
        o1.x = rnd_tf32(acc[ni][2]*inv1); o1.y = rnd_tf32(acc[ni][3]*inv1);
        *(float2*)(O0 + col) = o0;
        *(float2*)(O1 + col) = o1;
    }
}

// ---------------- launch ----------------
extern "C" void kernel_launch(void* const* d_in, const int* in_sizes, int n_in,
                              void* d_out, int out_size)
{
    const float* x1   = (const float*)d_in[0];
    const float* x2   = (const float*)d_in[1];
    const float* x3   = (const float*)d_in[2];
    const float* xf1  = (const float*)d_in[3];
    const float* xf2  = (const float*)d_in[4];
    const float* xf3  = (const float*)d_in[5];
    const float* emb  = (const float*)d_in[6];
    const float* axw  = (const float*)d_in[7];
    const float* axb  = (const float*)d_in[8];
    const float* afw  = (const float*)d_in[9];
    const float* afb  = (const float*)d_in[10];
    const float* q_w  = (const float*)d_in[11];
    const float* q_b  = (const float*)d_in[12];
    const float* k_w  = (const float*)d_in[13];
    const float* k_b  = (const float*)d_in[14];
    const float* v_w  = (const float*)d_in[15];
    const float* v_b  = (const float*)d_in[16];
    const float* o_w  = (const float*)d_in[17];
    const float* o_b  = (const float*)d_in[18];
    float* out = (float*)d_out;

    float *mx, *mxf, *xn, *xfn, *Qp, *Kp, *Vp, *att;
    float *qw, *kw, *vw, *ow;
    cudaGetSymbolAddress((void**)&mx,  g_mod_x);
    cudaGetSymbolAddress((void**)&mxf, g_mod_xf);
    cudaGetSymbolAddress((void**)&xn,  g_xn);
    cudaGetSymbolAddress((void**)&xfn, g_xfn);
    cudaGetSymbolAddress((void**)&Qp,  g_Qh);
    cudaGetSymbolAddress((void**)&Kp,  g_Kh);
    cudaGetSymbolAddress((void**)&Vp,  g_Vh);
    cudaGetSymbolAddress((void**)&att, g_att);
    cudaGetSymbolAddress((void**)&qw,  g_qw);
    cudaGetSymbolAddress((void**)&kw,  g_kw);
    cudaGetSymbolAddress((void**)&vw,  g_vw);
    cudaGetSymbolAddress((void**)&ow,  g_ow);

    cudaFuncSetAttribute(attn_tc_kernel,
        cudaFuncAttributeMaxDynamicSharedMemorySize, ATTN_SMEM_BYTES);
    cudaFuncSetAttribute(gemm_tc_kernel<0>,
        cudaFuncAttributeMaxDynamicSharedMemorySize, GEMM_SMEM);
    cudaFuncSetAttribute(gemm_tc_kernel<1>,
        cudaFuncAttributeMaxDynamicSharedMemorySize, GEMM_SMEM);

    // weight rounding (runs while LN path also proceeds)
    round_w_kernel<<<NB*Dd*Dd/1024,   256>>>(q_w, qw, NB*Dd*Dd/4);
    round_w_kernel<<<NB*Dd*DXFc/1024, 256>>>(k_w, kw, NB*Dd*DXFc/4);
    round_w_kernel<<<NB*Dd*DXFc/1024, 256>>>(v_w, vw, NB*Dd*DXFc/4);
    round_w_kernel<<<NB*Dd*Dd/1024,   256>>>(o_w, ow, NB*Dd*Dd/4);

    adaln_mod_kernel<<<dim3(2*Dd/256,   Bc, NB), 256>>>(emb, axw, axb, mx,  2*Dd);
    adaln_mod_kernel<<<dim3(2*DXFc/256, Bc, NB), 256>>>(emb, afw, afb, mxf, 2*DXFc);

    ln_mod_kernel<<<NB*Bc*Tt, 256>>>(x1, x2, x3, mx,  xn,  Dd,   Bc*Tt, Tt);
    ln_mod_kernel<<<NB*Bc*Nf, 256>>>(xf1, xf2, xf3, mxf, xfn, DXFc, Bc*Nf, Nf);

    gemm_tc_kernel<0><<<dim3(Bc*Tt/128, Dd/128, NB), 256, GEMM_SMEM>>>(
        xn, qw, q_b, Qp, qw, q_b, Qp, Bc*Tt, Dd, Dd, Tt);
    gemm_tc_kernel<0><<<dim3(Bc*Nf/128, Dd/128, 2*NB), 256, GEMM_SMEM>>>(
        xfn, kw, k_b, Kp, vw, v_b, Vp, Bc*Nf, Dd, DXFc, Nf);

    attn_tc_kernel<<<dim3(SQ/128, BHc), 256, ATTN_SMEM_BYTES>>>(Qp, Kp, Vp, att);

    gemm_tc_kernel<1><<<dim3(Bc*Tt/128, Dd/128, NB), 256, GEMM_SMEM>>>(
        att, ow, o_b, out, ow, o_b, out, Bc*Tt, Dd, Dd, Tt);
}